// round 8
// baseline (speedup 1.0000x reference)
#include <cuda_runtime.h>
#include <cuda_bf16.h>
#include <stdint.h>

#define B_ 128
#define T_ 1024
#define I_ 64
#define W_ 32
#define H_ 256
#define BT_ (B_*T_)

// ---------------- scratch (__device__ globals are allowed) ------------------
__device__ float g_e     [(size_t)BT_*H_];   // [T][B][H]
__device__ float g_pre_ho[(size_t)BT_*H_];   // [T][B][H]
__device__ float g_pre_i [(size_t)BT_*H_];
__device__ float g_pre_g [(size_t)BT_*H_];
__device__ float g_pre_f [(size_t)BT_*H_];
__device__ float g_pre_o [(size_t)BT_*H_];

__device__ __forceinline__ float sigm(float x) { return 1.f / (1.f + __expf(-x)); }

__device__ __forceinline__ uint32_t smem_u32(const void* p) {
    uint32_t a;
    asm("{ .reg .u64 t; cvta.to.shared.u64 t, %1; cvt.u32.u64 %0, t; }" : "=r"(a) : "l"(p));
    return a;
}
#define CLUSTER_SYNC() do { \
    asm volatile("barrier.cluster.arrive.aligned;" ::: "memory"); \
    asm volatile("barrier.cluster.wait.aligned;"   ::: "memory"); \
} while (0)

// ========================== Kernel E: e = sigmoid(xw @ w_e^T + b_e) =========
__global__ void k_e(const float* __restrict__ xw, const float* __restrict__ w_e,
                    const float* __restrict__ b_e)
{
    __shared__ float sx[8][32];
    int h = threadIdx.x;               // 0..255 output column
    int bt0 = blockIdx.x * 8;          // flat bt = b*T + t
    {
        int p = h >> 5, k = h & 31;
        int bt = bt0 + p;
        int b = bt >> 10, t = bt & 1023;
        sx[p][k] = xw[((size_t)b*T_ + t)*W_ + k];
    }
    __syncthreads();
    float4 wr[8];
    const float4* wp = (const float4*)(w_e + (size_t)h*W_);
#pragma unroll
    for (int u = 0; u < 8; ++u) wr[u] = wp[u];
    float bias = b_e[h];
#pragma unroll
    for (int p = 0; p < 8; ++p) {
        float acc = bias;
#pragma unroll
        for (int u = 0; u < 8; ++u) {
            acc += wr[u].x*sx[p][4*u+0] + wr[u].y*sx[p][4*u+1]
                 + wr[u].z*sx[p][4*u+2] + wr[u].w*sx[p][4*u+3];
        }
        int bt = bt0 + p;
        int b = bt >> 10, t = bt & 1023;
        g_e[((size_t)t*B_ + b)*H_ + h] = sigm(acc);
    }
}

// ================== Kernel X4: 4 x-GEMMs (K=64) + biases -> pre_{i,f,o,g} ===
// Row index m = t*B + b (matches [T][B][H] pre layout). Tile 64x64.
__global__ void k_x4(const float* __restrict__ x,
                     const float* __restrict__ w0, const float* __restrict__ w1,
                     const float* __restrict__ w2, const float* __restrict__ w3,
                     const float* __restrict__ bi, const float* __restrict__ bf,
                     const float* __restrict__ bo, const float* __restrict__ bg)
{
    __shared__ float A_s[64][68];
    __shared__ float B_s[64][68];
    int m0 = blockIdx.x * 64;
    int gy = blockIdx.y;
    int mat = gy >> 2;
    int col0 = (gy & 3) * 64;
    const float* w = (mat==0)?w0:(mat==1)?w1:(mat==2)?w2:w3;
    int tid = threadIdx.x;
    {
        int r = tid >> 2, q = tid & 3;
        int m = m0 + r;
        int b = m & (B_-1); int t = m >> 7;
        const float4* asrc = (const float4*)(x + ((size_t)b*T_ + t)*I_);
        const float4* bsrc = (const float4*)(w + (size_t)(col0 + r)*I_);
#pragma unroll
        for (int u = 0; u < 4; ++u) {
            float4 v = asrc[q + 4*u];
            int k = (q + 4*u) * 4;
            A_s[k+0][r]=v.x; A_s[k+1][r]=v.y; A_s[k+2][r]=v.z; A_s[k+3][r]=v.w;
        }
#pragma unroll
        for (int u = 0; u < 4; ++u) {
            float4 v = bsrc[q + 4*u];
            int k = (q + 4*u) * 4;
            B_s[k+0][r]=v.x; B_s[k+1][r]=v.y; B_s[k+2][r]=v.z; B_s[k+3][r]=v.w;
        }
    }
    __syncthreads();
    int tx = tid & 15, ty = tid >> 4;
    float acc[4][4] = {};
#pragma unroll 8
    for (int k = 0; k < 64; ++k) {
        float4 a = *(const float4*)&A_s[k][ty*4];
        float4 c = *(const float4*)&B_s[k][tx*4];
        float av[4] = {a.x,a.y,a.z,a.w};
        float bv[4] = {c.x,c.y,c.z,c.w};
#pragma unroll
        for (int i = 0; i < 4; ++i)
#pragma unroll
            for (int j = 0; j < 4; ++j) acc[i][j] += av[i]*bv[j];
    }
    const float* bias = (mat==0)?bi:(mat==1)?bf:(mat==2)?bo:bg;
    float* dst = (mat==0)?g_pre_i:(mat==1)?g_pre_f:(mat==2)?g_pre_o:g_pre_g;
    float4 bv4 = *(const float4*)&bias[col0 + tx*4];
#pragma unroll
    for (int i = 0; i < 4; ++i) {
        size_t off = (size_t)(m0 + ty*4 + i)*H_ + col0 + tx*4;
        float4 v = make_float4(acc[i][0]+bv4.x, acc[i][1]+bv4.y,
                               acc[i][2]+bv4.z, acc[i][3]+bv4.w);
        *(float4*)&dst[off] = v;
    }
}

// ============ Kernel HO: pre_ho = xd@w_d^T + xw@w_w^T + xm@w_m^T + b_e ======
__global__ void k_ho(const float* __restrict__ x,
                     const float* __restrict__ w_d, const float* __restrict__ w_w,
                     const float* __restrict__ w_m, const float* __restrict__ b_e)
{
    __shared__ float A_s[64][68];
    __shared__ float B_s[64][68];
    int m0 = blockIdx.x * 64;
    int col0 = blockIdx.y * 64;
    int tid = threadIdx.x;
    int tx = tid & 15, ty = tid >> 4;
    float acc[4][4] = {};
    const int shifts[3] = {1, 7, 30};
#pragma unroll
    for (int s = 0; s < 3; ++s) {
        const float* ws = (s==0)?w_d:(s==1)?w_w:w_m;
        __syncthreads();
        {
            int r = tid >> 2, q = tid & 3;
            int m = m0 + r;
            int b = m & (B_-1); int t = m >> 7;
            int bs = b - shifts[s];
#pragma unroll
            for (int u = 0; u < 4; ++u) {
                float4 v = make_float4(0.f,0.f,0.f,0.f);
                if (bs >= 0) v = ((const float4*)(x + ((size_t)bs*T_ + t)*I_))[q + 4*u];
                int k = (q + 4*u) * 4;
                A_s[k+0][r]=v.x; A_s[k+1][r]=v.y; A_s[k+2][r]=v.z; A_s[k+3][r]=v.w;
            }
            const float4* bsrc = (const float4*)(ws + (size_t)(col0 + r)*I_);
#pragma unroll
            for (int u = 0; u < 4; ++u) {
                float4 v = bsrc[q + 4*u];
                int k = (q + 4*u) * 4;
                B_s[k+0][r]=v.x; B_s[k+1][r]=v.y; B_s[k+2][r]=v.z; B_s[k+3][r]=v.w;
            }
        }
        __syncthreads();
#pragma unroll 8
        for (int k = 0; k < 64; ++k) {
            float4 a = *(const float4*)&A_s[k][ty*4];
            float4 c = *(const float4*)&B_s[k][tx*4];
            float av[4] = {a.x,a.y,a.z,a.w};
            float bv[4] = {c.x,c.y,c.z,c.w};
#pragma unroll
            for (int i = 0; i < 4; ++i)
#pragma unroll
                for (int j = 0; j < 4; ++j) acc[i][j] += av[i]*bv[j];
        }
    }
    float4 bv4 = *(const float4*)&b_e[col0 + tx*4];
#pragma unroll
    for (int i = 0; i < 4; ++i) {
        size_t off = (size_t)(m0 + ty*4 + i)*H_ + col0 + tx*4;
        float4 v = make_float4(acc[i][0]+bv4.x, acc[i][1]+bv4.y,
                               acc[i][2]+bv4.z, acc[i][3]+bv4.w);
        *(float4*)&g_pre_ho[off] = v;
    }
}

// ============ Kernel E3: pre_{i,f,o} += e @ {w_ie,w_fe,w_oe}^T (K=256) ======
__global__ void k_e3(const float* __restrict__ w_ie, const float* __restrict__ w_fe,
                     const float* __restrict__ w_oe)
{
    __shared__ float A_s[64][68];
    __shared__ float B_s[64][68];
    int m0 = blockIdx.x * 64;
    int gy = blockIdx.y;
    int mat = gy >> 2;
    int col0 = (gy & 3) * 64;
    const float* w = (mat==0)?w_ie:(mat==1)?w_fe:w_oe;
    float* dst = (mat==0)?g_pre_i:(mat==1)?g_pre_f:g_pre_o;
    int tid = threadIdx.x;
    int tx = tid & 15, ty = tid >> 4;
    float acc[4][4] = {};
    for (int kc = 0; kc < 4; ++kc) {
        __syncthreads();
        {
            int r = tid >> 2, q = tid & 3;
            const float4* asrc = (const float4*)(g_e + (size_t)(m0 + r)*H_ + kc*64);
            const float4* bsrc = (const float4*)(w   + (size_t)(col0 + r)*H_ + kc*64);
#pragma unroll
            for (int u = 0; u < 4; ++u) {
                float4 v = asrc[q + 4*u];
                int k = (q + 4*u) * 4;
                A_s[k+0][r]=v.x; A_s[k+1][r]=v.y; A_s[k+2][r]=v.z; A_s[k+3][r]=v.w;
            }
#pragma unroll
            for (int u = 0; u < 4; ++u) {
                float4 v = bsrc[q + 4*u];
                int k = (q + 4*u) * 4;
                B_s[k+0][r]=v.x; B_s[k+1][r]=v.y; B_s[k+2][r]=v.z; B_s[k+3][r]=v.w;
            }
        }
        __syncthreads();
#pragma unroll 8
        for (int k = 0; k < 64; ++k) {
            float4 a = *(const float4*)&A_s[k][ty*4];
            float4 c = *(const float4*)&B_s[k][tx*4];
            float av[4] = {a.x,a.y,a.z,a.w};
            float bv[4] = {c.x,c.y,c.z,c.w};
#pragma unroll
            for (int i = 0; i < 4; ++i)
#pragma unroll
                for (int j = 0; j < 4; ++j) acc[i][j] += av[i]*bv[j];
        }
    }
#pragma unroll
    for (int i = 0; i < 4; ++i) {
        size_t off = (size_t)(m0 + ty*4 + i)*H_ + col0 + tx*4;
        float4 old = *(const float4*)&dst[off];
        float4 v = make_float4(old.x+acc[i][0], old.y+acc[i][1],
                               old.z+acc[i][2], old.w+acc[i][3]);
        *(float4*)&dst[off] = v;
    }
}

// ======================= Recurrence (clustered persistent) ==================
// 16 clusters x 8 CTAs, 256 thr/CTA. Cluster g = batch rows [8g, 8g+8).
// CTA rank j owns H-columns [32j, 32j+32); slices of all 5 weights in SMEM.
// Thread roles (same tid split): compute (colA = tid&31, q = tid>>5, k-range
// 32q..32q+32), reduction (rowR = tid>>5, colR = tid&31).
// SMEM (floats): wt[32][260], g4[32][257] float4 (ih,gh,fo,oh), hn[8][260],
// ho[8][260], partials 8*8*32 float4.
#define REC_WT_F   (32*260)
#define REC_G4_F   (32*257*4)
#define REC_HB_F   (8*260)
#define REC_PP_F   (8*8*32*4)
#define REC_SMEM_FLOATS (REC_WT_F + REC_G4_F + 2*REC_HB_F + REC_PP_F)
#define REC_SMEM_BYTES  (REC_SMEM_FLOATS*4)

__global__ void __cluster_dims__(8,1,1) __launch_bounds__(256,1)
k_rec(const float* __restrict__ w_t, const float* __restrict__ w_ih,
      const float* __restrict__ w_gh, const float* __restrict__ w_fo,
      const float* __restrict__ w_oh, float* __restrict__ out)
{
    extern __shared__ float sm[];
    float*  wt_s = sm;
    float4* g4_s = (float4*)(sm + REC_WT_F);
    float*  hn_s = sm + REC_WT_F + REC_G4_F;
    float*  ho_s = hn_s + REC_HB_F;
    float4* pp4  = (float4*)(ho_s + REC_HB_F);
    float*  pp1  = (float*)pp4;

    int tid = threadIdx.x;
    int j = blockIdx.x & 7;        // cluster rank = H-slice
    int g = blockIdx.x >> 3;       // cluster id = batch group

    // ---- load weight slices ----
    for (int idx = tid; idx < 32*64; idx += 256) {        // w_t: 32 cols x 64 f4
        int col = idx >> 6, kq = idx & 63;
        float4 v = *(const float4*)(w_t + ((size_t)(j*32+col))*H_ + kq*4);
        *(float4*)&wt_s[col*260 + kq*4] = v;
    }
    for (int idx = tid; idx < 32*256; idx += 256) {       // gate mats interleaved
        int col = idx >> 8, k = idx & 255;
        size_t o = (size_t)(j*32+col)*H_ + k;
        float4 v;
        v.x = w_ih[o]; v.y = w_gh[o]; v.z = w_fo[o]; v.w = w_oh[o];
        g4_s[col*257 + k] = v;
    }
    for (int idx = tid; idx < REC_HB_F; idx += 256) hn_s[idx] = 0.f;
    __syncthreads();
    CLUSTER_SYNC();

    int colA = tid & 31, q = tid >> 5;
    int rowR = q,        colR = colA;
    int cg   = j*32 + colR;          // global H column this thread finalizes
    int brow = g*8 + rowR;           // global batch row this thread finalizes
    int k0   = q*32;
    float c_state = 0.f;
    uint32_t ho_local = smem_u32(&ho_s[rowR*260 + cg]);
    uint32_t hn_local = smem_u32(&hn_s[rowR*260 + cg]);

    for (int t = 0; t < T_; ++t) {
        // prefetch pre-activations (consumed much later -> latency hidden)
        size_t pbase = ((size_t)t*B_ + brow)*H_ + cg;
        float pho = g_pre_ho[pbase];
        float pi  = g_pre_i [pbase];
        float pg  = g_pre_g [pbase];
        float pf  = g_pre_f [pbase];
        float po  = g_pre_o [pbase];

        // ---- phase 1: partial h_o = h_{t-1} @ w_t^T over k-range ----
        float a1[8] = {0.f,0.f,0.f,0.f,0.f,0.f,0.f,0.f};
#pragma unroll
        for (int kb = 0; kb < 32; kb += 4) {
            int k = k0 + kb;
            float4 wv = *(const float4*)&wt_s[colA*260 + k];
            float4 hv[8];
#pragma unroll
            for (int r = 0; r < 8; ++r) hv[r] = *(const float4*)&hn_s[r*260 + k];
#pragma unroll
            for (int r = 0; r < 8; ++r)
                a1[r] += wv.x*hv[r].x + wv.y*hv[r].y + wv.z*hv[r].z + wv.w*hv[r].w;
        }
#pragma unroll
        for (int r = 0; r < 8; ++r) pp1[(r*8 + q)*32 + colA] = a1[r];
        __syncthreads();
        float s1 = pho;
#pragma unroll
        for (int qq = 0; qq < 8; ++qq) s1 += pp1[(rowR*8 + qq)*32 + colR];
        float hov = sigm(s1);
        // broadcast h_o to every CTA in the cluster (incl. self)
#pragma unroll
        for (int p = 0; p < 8; ++p) {
            uint32_t ra;
            asm volatile("mapa.shared::cluster.u32 %0, %1, %2;"
                         : "=r"(ra) : "r"(ho_local), "r"(p));
            asm volatile("st.shared::cluster.f32 [%0], %1;"
                         :: "r"(ra), "f"(hov) : "memory");
        }
        CLUSTER_SYNC();

        // ---- phase 2: partial (i,g,f,o) = h_o @ W^T over k-range ----
        float ai[8]={0,0,0,0,0,0,0,0}, ag[8]={0,0,0,0,0,0,0,0};
        float af[8]={0,0,0,0,0,0,0,0}, ao[8]={0,0,0,0,0,0,0,0};
#pragma unroll
        for (int kb = 0; kb < 32; kb += 4) {
            int k = k0 + kb;
            float4 hv[8];
#pragma unroll
            for (int r = 0; r < 8; ++r) hv[r] = *(const float4*)&ho_s[r*260 + k];
#pragma unroll
            for (int kk = 0; kk < 4; ++kk) {
                float4 w = g4_s[colA*257 + k + kk];
#pragma unroll
                for (int r = 0; r < 8; ++r) {
                    float hh = (kk==0)?hv[r].x:(kk==1)?hv[r].y:(kk==2)?hv[r].z:hv[r].w;
                    ai[r] += w.x*hh; ag[r] += w.y*hh;
                    af[r] += w.z*hh; ao[r] += w.w*hh;
                }
            }
        }
#pragma unroll
        for (int r = 0; r < 8; ++r)
            pp4[(r*8 + q)*32 + colA] = make_float4(ai[r], ag[r], af[r], ao[r]);
        __syncthreads();
        float si = pi, sg = pg, sf = pf, so = po;
#pragma unroll
        for (int qq = 0; qq < 8; ++qq) {
            float4 v = pp4[(rowR*8 + qq)*32 + colR];
            si += v.x; sg += v.y; sf += v.z; so += v.w;
        }
        float iv = sigm(si), gv = tanhf(sg), fv = sigm(sf), ov = sigm(so);
        c_state = fv*c_state + iv*gv;
        float hnv = ov * tanhf(c_state);

        size_t obase = ((size_t)brow*T_ + t)*H_ + cg;
        out[obase] = hnv;
        out[(size_t)BT_*H_ + obase] = c_state;

        // broadcast h_{t} to every CTA in the cluster
#pragma unroll
        for (int p = 0; p < 8; ++p) {
            uint32_t ra;
            asm volatile("mapa.shared::cluster.u32 %0, %1, %2;"
                         : "=r"(ra) : "r"(hn_local), "r"(p));
            asm volatile("st.shared::cluster.f32 [%0], %1;"
                         :: "r"(ra), "f"(hnv) : "memory");
        }
        CLUSTER_SYNC();
    }
}

// ============================== launch ======================================
extern "C" void kernel_launch(void* const* d_in, const int* in_sizes, int n_in,
                              void* d_out, int out_size)
{
    const float* x    = (const float*)d_in[0];
    const float* xw   = (const float*)d_in[1];
    const float* w_ix = (const float*)d_in[2];
    const float* w_ih = (const float*)d_in[3];
    const float* w_ie = (const float*)d_in[4];
    const float* b_i  = (const float*)d_in[5];
    const float* w_fx = (const float*)d_in[6];
    const float* w_fo = (const float*)d_in[7];
    const float* w_fe = (const float*)d_in[8];
    const float* b_f  = (const float*)d_in[9];
    const float* w_ox = (const float*)d_in[10];
    const float* w_oh = (const float*)d_in[11];
    const float* w_oe = (const float*)d_in[12];
    const float* b_o  = (const float*)d_in[13];
    const float* w_gx = (const float*)d_in[14];
    const float* w_gh = (const float*)d_in[15];
    const float* b_g  = (const float*)d_in[16];
    const float* w_d  = (const float*)d_in[17];
    const float* w_w  = (const float*)d_in[18];
    const float* w_m  = (const float*)d_in[19];
    const float* w_t  = (const float*)d_in[20];
    const float* w_e  = (const float*)d_in[21];
    const float* b_e  = (const float*)d_in[22];
    float* out = (float*)d_out;

    k_e <<<BT_/8, 256>>>(xw, w_e, b_e);
    k_x4<<<dim3(BT_/64, 16), 256>>>(x, w_ix, w_fx, w_ox, w_gx, b_i, b_f, b_o, b_g);
    k_ho<<<dim3(BT_/64, 4), 256>>>(x, w_d, w_w, w_m, b_e);
    k_e3<<<dim3(BT_/64, 12), 256>>>(w_ie, w_fe, w_oe);

    static int smem_set = 0;
    if (!smem_set) {
        cudaFuncSetAttribute(k_rec, cudaFuncAttributeMaxDynamicSharedMemorySize,
                             REC_SMEM_BYTES);
        smem_set = 1;
    }
    k_rec<<<128, 256, REC_SMEM_BYTES>>>(w_t, w_ih, w_gh, w_fo, w_oh, out);
}